// round 8
// baseline (speedup 1.0000x reference)
#include <cuda_runtime.h>
#include <cuda_bf16.h>
#include <cstdint>

#ifndef __CUDA_ARCH_HAS_FEATURE__
#define __CUDA_ARCH_HAS_FEATURE__(x) 0
#endif
#if defined(__CUDA_ARCH_FEAT_SM103_ALL) || __CUDA_ARCH_HAS_FEATURE__(SM103_ALL) || \
    defined(__CUDA_ARCH_FEAT_SM100_ALL) || __CUDA_ARCH_HAS_FEATURE__(SM100_ALL)
#define HAS_TCGEN05 1
#else
#define HAS_TCGEN05 0
#endif

static constexpr int BB  = 65536;
static constexpr int DD  = 512;
static constexpr int HH1 = 256;
static constexpr int HH2 = 128;
static constexpr int NTILES = BB / 128;   // 512
static constexpr int GRID = 148;

__device__ __nv_bfloat16 g_w1t[HH1 * DD];
__device__ __nv_bfloat16 g_w2t[HH2 * HH1];
__device__ __nv_bfloat16 g_w3t[64 * HH2];
__device__ __nv_bfloat16 g_tt [64 * DD];

// ---------------- PTX helpers ----------------------------------------------
__device__ __forceinline__ uint32_t smem_u32(const void* p) {
    uint32_t a;
    asm("{ .reg .u64 t; cvta.to.shared.u64 t, %1; cvt.u32.u64 %0, t; }" : "=r"(a) : "l"(p));
    return a;
}
#define MBAR_INIT(addr, cnt) \
    asm volatile("mbarrier.init.shared.b64 [%0], %1;" :: "r"(addr), "r"(cnt) : "memory")
#define MBAR_ARRIVE(addr) \
    asm volatile("mbarrier.arrive.shared.b64 _, [%0];" :: "r"(addr) : "memory")
#define MBAR_WAIT(addr, parity) do {                                              \
    asm volatile("{\n\t.reg .pred P;\n\tWL%=:\n\t"                                \
        "mbarrier.try_wait.parity.acquire.cta.shared::cta.b64 P, [%0], %1, 0x989680;\n\t" \
        "@P bra.uni WD%=;\n\tbra.uni WL%=;\n\tWD%=:\n\t}"                          \
        :: "r"(addr), "r"(parity) : "memory");                                    \
} while (0)
#define TC_ALLOC(smem_dst, n) \
    asm volatile("tcgen05.alloc.cta_group::1.sync.aligned.shared::cta.b32 [%0], %1;" :: "r"(smem_dst), "r"(n) : "memory")
#define TC_DEALLOC(tmem, n) \
    asm volatile("tcgen05.dealloc.cta_group::1.sync.aligned.b32 %0, %1;" :: "r"(tmem), "r"(n))
#define TC_RELINQ() \
    asm volatile("tcgen05.relinquish_alloc_permit.cta_group::1.sync.aligned;")
#define TC_COMMIT(mbar) \
    asm volatile("tcgen05.commit.cta_group::1.mbarrier::arrive::one.shared::cluster.b64 [%0];" :: "r"(mbar) : "memory")
#define TC_FENCE_AFTER()   asm volatile("tcgen05.fence::after_thread_sync;" ::: "memory")
#define TC_FENCE_BEFORE()  asm volatile("tcgen05.fence::before_thread_sync;" ::: "memory")
#define TC_WAIT_LD()       asm volatile("tcgen05.wait::ld.sync.aligned;" ::: "memory")
#define TC_WAIT_ST()       asm volatile("tcgen05.wait::st.sync.aligned;" ::: "memory")
#define FENCE_ASYNC()      asm volatile("fence.proxy.async.shared::cta;" ::: "memory")
#define BARC()             asm volatile("bar.sync 1, 256;" ::: "memory")

#define TC_LD_X32(r, tmem_addr) \
    asm volatile( \
        "tcgen05.ld.sync.aligned.32x32b.x32.b32 " \
        "{%0, %1, %2, %3, %4, %5, %6, %7, " \
        " %8, %9, %10, %11, %12, %13, %14, %15, " \
        " %16, %17, %18, %19, %20, %21, %22, %23, " \
        " %24, %25, %26, %27, %28, %29, %30, %31}, [%32];" \
        : "=r"((r)[0]),  "=r"((r)[1]),  "=r"((r)[2]),  "=r"((r)[3]), \
          "=r"((r)[4]),  "=r"((r)[5]),  "=r"((r)[6]),  "=r"((r)[7]), \
          "=r"((r)[8]),  "=r"((r)[9]),  "=r"((r)[10]), "=r"((r)[11]), \
          "=r"((r)[12]), "=r"((r)[13]), "=r"((r)[14]), "=r"((r)[15]), \
          "=r"((r)[16]), "=r"((r)[17]), "=r"((r)[18]), "=r"((r)[19]), \
          "=r"((r)[20]), "=r"((r)[21]), "=r"((r)[22]), "=r"((r)[23]), \
          "=r"((r)[24]), "=r"((r)[25]), "=r"((r)[26]), "=r"((r)[27]), \
          "=r"((r)[28]), "=r"((r)[29]), "=r"((r)[30]), "=r"((r)[31]) \
        : "r"(tmem_addr))

#define TC_ST_X16(tmem_addr, r) \
    asm volatile( \
        "tcgen05.st.sync.aligned.32x32b.x16.b32 [%0], " \
        "{%1, %2, %3, %4, %5, %6, %7, %8, " \
        " %9, %10, %11, %12, %13, %14, %15, %16};" \
        :: "r"(tmem_addr), \
           "r"((r)[0]),  "r"((r)[1]),  "r"((r)[2]),  "r"((r)[3]), \
           "r"((r)[4]),  "r"((r)[5]),  "r"((r)[6]),  "r"((r)[7]), \
           "r"((r)[8]),  "r"((r)[9]),  "r"((r)[10]), "r"((r)[11]), \
           "r"((r)[12]), "r"((r)[13]), "r"((r)[14]), "r"((r)[15]) \
        : "memory")

#if HAS_TCGEN05
__device__ __forceinline__ void mma_f16_ss(uint32_t d, uint64_t ad, uint64_t bd,
                                           uint32_t idesc, uint32_t en) {
    asm volatile(
        "{\n\t.reg .pred p;\n\tsetp.ne.u32 p, %4, 0;\n\t"
        "tcgen05.mma.cta_group::1.kind::f16 [%0], %1, %2, %3, {%5, %5, %5, %5}, p;\n\t}"
        :: "r"(d), "l"(ad), "l"(bd), "r"(idesc), "r"(en), "r"(0u) : "memory");
}
__device__ __forceinline__ void mma_f16_ts(uint32_t d, uint32_t a_tmem, uint64_t bd,
                                           uint32_t idesc, uint32_t en) {
    asm volatile(
        "{\n\t.reg .pred p;\n\tsetp.ne.u32 p, %4, 0;\n\t"
        "tcgen05.mma.cta_group::1.kind::f16 [%0], [%1], %2, %3, {%5, %5, %5, %5}, p;\n\t}"
        :: "r"(d), "r"(a_tmem), "l"(bd), "r"(idesc), "r"(en), "r"(0u) : "memory");
}
#endif

__device__ __forceinline__ uint64_t make_desc(uint32_t addr) {
    const uint64_t base = (2ull << 61) | (1ull << 46) | (64ull << 32) | (1ull << 16);
    return base | ((uint64_t)(addr >> 4) & 0x3FFF);
}
__device__ __forceinline__ uint32_t sw128(uint32_t o) { return o ^ ((o >> 3) & 0x70); }
__device__ __forceinline__ uint32_t pack_bf2(float a, float b) {
    uint32_t r;
    asm("cvt.rn.satfinite.bf16x2.f32 %0, %1, %2;" : "=r"(r) : "f"(b), "f"(a));
    return r;
}
static __host__ __device__ constexpr uint32_t idesc_n(int N) {
    return (1u << 4) | (1u << 7) | (1u << 10) | ((uint32_t)(N / 8) << 17) | (8u << 24);
}

// ---- FFMA-only ln/exp ------------------------------------------------------
__device__ __forceinline__ float vlnf(float x) {
    int i = __float_as_int(x);
    float e = (float)((i >> 23) - 126);
    float m = __int_as_float((i & 0x007FFFFF) | 0x3F000000);
    if (m < 0.70710678f) { m += m; e -= 1.0f; }
    float z = m - 1.0f, w = z * z;
    float p =              7.0376836292e-2f;
    p = fmaf(p, z, -1.1514610310e-1f);
    p = fmaf(p, z,  1.1676998740e-1f);
    p = fmaf(p, z, -1.2420140846e-1f);
    p = fmaf(p, z,  1.4249322787e-1f);
    p = fmaf(p, z, -1.6668057665e-1f);
    p = fmaf(p, z,  2.0000714765e-1f);
    p = fmaf(p, z, -2.4999993993e-1f);
    p = fmaf(p, z,  3.3333331174e-1f);
    float r = fmaf(z * w, p, fmaf(-0.5f, w, z));
    return fmaf(e, 0.693147180559945f, r);
}
__device__ __forceinline__ float vexpf(float x) {
    float t = fmaxf(x * 1.4426950408889634f, -125.0f);
    int ni = __float2int_rn(t);
    float f = t - (float)ni;
    float p =              1.53533619e-4f;
    p = fmaf(p, f, 1.33988744e-3f);
    p = fmaf(p, f, 9.61843736e-3f);
    p = fmaf(p, f, 5.55033250e-2f);
    p = fmaf(p, f, 2.40226479e-1f);
    p = fmaf(p, f, 6.93147203e-1f);
    p = fmaf(p, f, 1.0f);
    return p * __int_as_float((ni + 127) << 23);
}
__device__ __forceinline__ float temp_of(float ep) {
    return fmaxf(0.1f, 10.0f * vexpf(-4.60517018598809f * ep * 0.001f));
}

// ---------------- weight transpose + bf16 convert ---------------------------
__global__ void transpose_all(const float* __restrict__ W1, const float* __restrict__ W2,
                              const float* __restrict__ W3, const float* __restrict__ Th,
                              __nv_bfloat16* __restrict__ w1t, __nv_bfloat16* __restrict__ w2t,
                              __nv_bfloat16* __restrict__ w3t, __nv_bfloat16* __restrict__ tt)
{
    int idx = blockIdx.x * 256 + threadIdx.x;
    if (idx < 131072) {
        int r = idx >> 8, c = idx & 255;
        w1t[c * DD + r] = __float2bfloat16(W1[idx]);
    } else if (idx < 163840) {
        int q = idx - 131072; int r = q >> 7, c = q & 127;
        w2t[c * HH1 + r] = __float2bfloat16(W2[q]);
    } else if (idx < 172032) {
        int q = idx - 163840; int r = q >> 6, c = q & 63;
        w3t[c * HH2 + r] = __float2bfloat16(W3[q]);
    } else if (idx < 204800) {
        int q = idx - 172032; int r = q >> 6, c = q & 63;
        tt[c * DD + r] = __float2bfloat16(Th[q]);
    }
}

// ---------------- SMEM map --------------------------------------------------
static constexpr int SMEM_SIZE = 204800;

__global__ __launch_bounds__(512, 1) void fused_llp(
    const float* __restrict__ x, const float* __restrict__ u,
    const float* __restrict__ label,
    const __nv_bfloat16* __restrict__ w1t, const __nv_bfloat16* __restrict__ w2t,
    const __nv_bfloat16* __restrict__ w3t, const __nv_bfloat16* __restrict__ tt,
    const float* __restrict__ b1, const float* __restrict__ b2,
    const float* __restrict__ b3, const int* __restrict__ epochp,
    float* __restrict__ out)
{
#if HAS_TCGEN05
    constexpr uint32_t CHF0 = 8, CFR0 = 24, P1D = 40, P2D = 48, P3D = 56, P4D = 64, P5D = 72;
    constexpr uint32_t B1O = 128, B2O = 1152, B3O = 1664;
    constexpr uint32_t PMX = 2048, PSM = 3072, PDT = 4096, RED = 5120;
    constexpr uint32_t ASL = 8192, BSL = 40960, W2TO = 122880, W3TO = 188416;
    constexpr uint32_t IDB1 = idesc_n(256), IDT = idesc_n(64);
    constexpr uint32_t IDB2 = idesc_n(128), IDB3 = idesc_n(64);
    // TMEM: h1 f32 @0-255 (bf16 reuse @0-127) | xt @256-319 | h2 f32 @320-447
    //       (bf16 reuse @320-383) | logits @448-511

    extern __shared__ char smem[];
    const uint32_t sb = smem_u32(smem);
    const int tid = threadIdx.x;
    const int wid = tid >> 5;
    const int lane = tid & 31;

    // ---------------- prologue (all threads) ----------------
    if (wid == 0) TC_ALLOC(sb + 0, 512);
    if (tid == 0) {
        MBAR_INIT(sb + CHF0, 128);  MBAR_INIT(sb + CHF0 + 8, 128);
        MBAR_INIT(sb + CFR0, 1);    MBAR_INIT(sb + CFR0 + 8, 1);
        MBAR_INIT(sb + P1D, 1); MBAR_INIT(sb + P2D, 1); MBAR_INIT(sb + P3D, 1);
        MBAR_INIT(sb + P4D, 1); MBAR_INIT(sb + P5D, 1);
    }
    if (tid < 256) ((float*)(smem + B1O))[tid] = b1[tid];
    else if (tid < 384) ((float*)(smem + B2O))[tid - 256] = b2[tid - 256];
    else if (tid < 448) ((float*)(smem + B3O))[tid - 384] = b3[tid - 384];
    // W2T: 128 rows x 256k -> 4 K-blocks of 128x64 (16KB each)
#pragma unroll
    for (int i = 0; i < 8; i++) {
        int q = tid + i * 512;
        int n = q >> 5, j = q & 31, kb = j >> 3, ku = j & 7;
        uint4 v = *(const uint4*)(w2t + (size_t)n * HH1 + j * 8);
        *(uint4*)(smem + W2TO + kb * 16384 + sw128(n * 128 + ku * 16)) = v;
    }
    // W3T: 64 rows x 128k -> 2 K-blocks of 64x64 (8KB each)
#pragma unroll
    for (int i = 0; i < 2; i++) {
        int q = tid + i * 512;
        int n = q >> 4, j = q & 15, kb = j >> 3, ku = j & 7;
        uint4 v = *(const uint4*)(w3t + (size_t)n * HH2 + j * 8);
        *(uint4*)(smem + W3TO + kb * 8192 + sw128(n * 128 + ku * 16)) = v;
    }
    FENCE_ASYNC();
    __syncthreads();
    uint32_t tmem;
    asm volatile("ld.shared.b32 %0, [%1];" : "=r"(tmem) : "r"(sb + 0));

    const float tinv = 1.0f / temp_of((float)(*epochp));

    // =======================================================================
    if (wid >= 12) {
        // ---------------- PRODUCERS (warps 12-15, 128 threads) -------------
        const int pt = tid - 384;
        int cfree[2] = {0, 0};
        int gc = 0;
        for (int t = blockIdx.x; t < NTILES; t += GRID) {
            const int m0 = t * 128;
            for (int c = 0; c < 8; c++) {
                const int slot = gc & 1;
                if (gc >= 2) { MBAR_WAIT(sb + CFR0 + 8 * slot, cfree[slot] & 1); cfree[slot]++; }
#pragma unroll
                for (int i = 0; i < 8; i++) {
                    int q = pt + i * 128;
                    int row = q >> 3, ku = q & 7;
                    const float4* src = (const float4*)(x + (size_t)(m0 + row) * DD + c * 64 + ku * 8);
                    float4 f0 = src[0], f1 = src[1];
                    uint4 v = make_uint4(pack_bf2(f0.x, f0.y), pack_bf2(f0.z, f0.w),
                                         pack_bf2(f1.x, f1.y), pack_bf2(f1.z, f1.w));
                    *(uint4*)(smem + ASL + slot * 16384 + sw128(row * 128 + ku * 16)) = v;
                }
#pragma unroll
                for (int i = 0; i < 20; i++) {
                    int q = pt + i * 128;
                    int row = q >> 3, ku = q & 7;
                    const __nv_bfloat16* src = (row >= 256) ? (tt + (size_t)(row - 256) * DD)
                                                            : (w1t + (size_t)row * DD);
                    uint4 v = *(const uint4*)(src + c * 64 + ku * 8);
                    *(uint4*)(smem + BSL + slot * 40960 + sw128(row * 128 + ku * 16)) = v;
                }
                FENCE_ASYNC();
                MBAR_ARRIVE(sb + CHF0 + 8 * slot);
                gc++;
            }
        }
    } else if (wid == 8) {
        // ---------------- MMA warp (lane 0 only) ---------------------------
        if (lane == 0) {
            int cful[2] = {0, 0};
            int p2c = 0, p4c = 0;
            int gc = 0;
            for (int t = blockIdx.x; t < NTILES; t += GRID) {
                for (int c = 0; c < 8; c++) {
                    const int slot = gc & 1;
                    MBAR_WAIT(sb + CHF0 + 8 * slot, cful[slot] & 1); cful[slot]++;
                    uint64_t ad = make_desc(sb + ASL + slot * 16384);
                    uint64_t bd = make_desc(sb + BSL + slot * 40960);
                    uint64_t td = make_desc(sb + BSL + slot * 40960 + 256 * 128);
#pragma unroll
                    for (int s = 0; s < 4; s++) {
                        uint32_t en = (c > 0 || s > 0) ? 1u : 0u;
                        mma_f16_ss(tmem, ad + 2 * s, bd + 2 * s, IDB1, en);
                        mma_f16_ss(tmem + 256, ad + 2 * s, td + 2 * s, IDT, en);
                    }
                    TC_COMMIT(sb + CFR0 + 8 * slot);
                    if (c == 7) TC_COMMIT(sb + P1D);
                    gc++;
                }
                // P3: h1bf16(TMEM 0-127) @ W2T -> h2 (K=256, 16 steps)
                MBAR_WAIT(sb + P2D, p2c & 1); p2c++;
                TC_FENCE_AFTER();
#pragma unroll
                for (int s = 0; s < 16; s++) {
                    uint64_t bd = make_desc(sb + W2TO + (uint32_t)(s >> 2) * 16384u) + (s & 3) * 2;
                    mma_f16_ts(tmem + 320, tmem + s * 8, bd, IDB2, s > 0 ? 1u : 0u);
                }
                TC_COMMIT(sb + P3D);
                // P5: h2bf16(TMEM 320-383) @ W3T -> logits (K=128, 8 steps)
                MBAR_WAIT(sb + P4D, p4c & 1); p4c++;
                TC_FENCE_AFTER();
#pragma unroll
                for (int s = 0; s < 8; s++) {
                    uint64_t bd = make_desc(sb + W3TO + (uint32_t)(s >> 2) * 8192u) + (s & 3) * 2;
                    mma_f16_ts(tmem + 448, tmem + 320 + s * 8, bd, IDB3, s > 0 ? 1u : 0u);
                }
                TC_COMMIT(sb + P5D);
            }
        }
    } else if (wid < 8) {
        // ---------------- CONSUMERS (warps 0-7, 256 threads) ---------------
        // Warp w accesses TMEM subpartition (w&3): rows (w&3)*32+lane.
        // Column split: half = w>>2 covers its half of the columns.
        const int w = wid;
        const int sub = w & 3;
        const int half = w >> 2;
        const int tr = sub * 32 + lane;
        int cp1 = 0, cp3 = 0, cp5 = 0;
        float acc = 0.f;
        const float* sb1 = (const float*)(smem + B1O);
        const float* sb2 = (const float*)(smem + B2O);
        const float* sb3 = (const float*)(smem + B3O);
        float* pmax = (float*)(smem + PMX);
        float* psum = (float*)(smem + PSM);
        float* pdot = (float*)(smem + PDT);

        for (int t = blockIdx.x; t < NTILES; t += GRID) {
            const int m0 = t * 128;
            // ---- P2: h1 epilogue -> TMEM bf16 ; xt -> regs ----
            MBAR_WAIT(sb + P1D, cp1 & 1); cp1++;
            TC_FENCE_AFTER();
            uint32_t pk[64];
            {
                uint32_t r[32];
#pragma unroll
                for (int ch = 0; ch < 4; ch++) {
                    const int cb = half * 128 + ch * 32;   // f32 cols of own rows
                    TC_LD_X32(r, tmem + cb);
                    TC_WAIT_LD();
#pragma unroll
                    for (int i = 0; i < 16; i++) {
                        float a = __uint_as_float(r[2 * i + 0]) + sb1[cb + 2 * i + 0];
                        float b = __uint_as_float(r[2 * i + 1]) + sb1[cb + 2 * i + 1];
                        pk[ch * 16 + i] = pack_bf2(fmaxf(a, 0.f), fmaxf(b, 0.f));
                    }
                }
            }
            BARC();                                        // all f32/bf16-target reads done
#pragma unroll
            for (int ch = 0; ch < 4; ch++)
                TC_ST_X16(tmem + half * 64 + ch * 16, pk + ch * 16);
            // xt -> regs (cols 256-319, safe until P2D gates next-tile P1)
            float xtv[32];
            {
                uint32_t r[32];
                TC_LD_X32(r, tmem + 256 + half * 32);
                TC_WAIT_LD();
#pragma unroll
                for (int j = 0; j < 32; j++) xtv[j] = __uint_as_float(r[j]);
            }
            TC_WAIT_ST();
            TC_FENCE_BEFORE();
            BARC();
            if (tid == 0) MBAR_ARRIVE(sb + P2D);

            // prefetch u + label for this tile
            float4 uu[8];
            {
                const float4* up = (const float4*)(u + (size_t)(m0 + tr) * 64 + half * 32);
#pragma unroll
                for (int q = 0; q < 8; q++) uu[q] = up[q];
            }
            float lb = 0.f;
            if (half == 0) lb = __ldg(&label[m0 + tr]);

            // ---- P4: h2 epilogue -> TMEM bf16 ----
            MBAR_WAIT(sb + P3D, cp3 & 1); cp3++;
            TC_FENCE_AFTER();
            uint32_t pk2[32];
            {
                uint32_t r[32];
#pragma unroll
                for (int ch = 0; ch < 2; ch++) {
                    const int cb = 320 + half * 64 + ch * 32;  // h2 f32 cols
                    TC_LD_X32(r, tmem + cb);
                    TC_WAIT_LD();
#pragma unroll
                    for (int i = 0; i < 16; i++) {
                        float a = __uint_as_float(r[2 * i + 0]) + sb2[cb - 320 + 2 * i + 0];
                        float b = __uint_as_float(r[2 * i + 1]) + sb2[cb - 320 + 2 * i + 1];
                        pk2[ch * 16 + i] = pack_bf2(fmaxf(a, 0.f), fmaxf(b, 0.f));
                    }
                }
            }
            BARC();
#pragma unroll
            for (int ch = 0; ch < 2; ch++)
                TC_ST_X16(tmem + 320 + half * 32 + ch * 16, pk2 + ch * 16);
            TC_WAIT_ST();
            TC_FENCE_BEFORE();
            BARC();
            if (tid == 0) MBAR_ARRIVE(sb + P4D);

            // ---- P6: gumbel softmax + row-dot + MSE ----
            MBAR_WAIT(sb + P5D, cp5 & 1); cp5++;
            TC_FENCE_AFTER();
            float s[32];
            {
                uint32_t r[32];
                TC_LD_X32(r, tmem + 448 + half * 32);
                TC_WAIT_LD();
#pragma unroll
                for (int j = 0; j < 32; j++) s[j] = __uint_as_float(r[j]) + sb3[half * 32 + j];
            }
            float mx = -1e30f;
#pragma unroll
            for (int q = 0; q < 8; q++) {
                float4 ug = uu[q];
                float g0 = -vlnf(-vlnf(ug.x));
                float g1 = -vlnf(-vlnf(ug.y));
                float g2 = -vlnf(-vlnf(ug.z));
                float g3 = -vlnf(-vlnf(ug.w));
                s[4 * q + 0] = (s[4 * q + 0] + g0) * tinv;
                s[4 * q + 1] = (s[4 * q + 1] + g1) * tinv;
                s[4 * q + 2] = (s[4 * q + 2] + g2) * tinv;
                s[4 * q + 3] = (s[4 * q + 3] + g3) * tinv;
                mx = fmaxf(mx, fmaxf(fmaxf(s[4 * q], s[4 * q + 1]), fmaxf(s[4 * q + 2], s[4 * q + 3])));
            }
            pmax[tr * 2 + half] = mx;
            BARC();
            mx = fmaxf(pmax[tr * 2], pmax[tr * 2 + 1]);
            float sum = 0.f, dot = 0.f;
#pragma unroll
            for (int j = 0; j < 32; j++) {
                float e = vexpf(s[j] - mx);
                sum += e;
                dot = fmaf(xtv[j], e, dot);
            }
            psum[tr * 2 + half] = sum;
            pdot[tr * 2 + half] = dot;
            BARC();
            if (half == 0) {
                float tsum = psum[tr * 2] + psum[tr * 2 + 1];
                float tdot = pdot[tr * 2] + pdot[tr * 2 + 1];
                float diff = tdot / tsum - lb;
                acc = fmaf(diff, diff, acc);
            }
        }
        // final reduction
        if (half == 0) {
            acc *= (1.0f / (float)BB);
#pragma unroll
            for (int o = 16; o; o >>= 1) acc += __shfl_xor_sync(0xffffffffu, acc, o);
            if (lane == 0) ((float*)(smem + RED))[w] = acc;
        }
    }

    __syncthreads();
    if (tid == 0) {
        float* red = (float*)(smem + RED);
        atomicAdd(out, red[0] + red[1] + red[2] + red[3]);
    }
    if (wid == 0) { TC_RELINQ(); TC_DEALLOC(tmem, 512); }

#else  // ------------------- SIMT fallback (generic PTX pass only) ----------
    extern __shared__ char smem[];
    float* red = (float*)smem;
    const int tid = threadIdx.x;
    const float tinv = 1.0f / temp_of((float)(*epochp));
    float accp = 0.f;
    for (int t = blockIdx.x; t < NTILES; t += GRID) {
        const int m0 = t * 128;
        if (tid < 128) {
            const int row = m0 + tid;
            float h1v[256], h2v[128], d[64];
            for (int n = 0; n < 256; n++) {
                float a2 = b1[n];
                const __nv_bfloat16* w = w1t + (size_t)n * DD;
                for (int k = 0; k < DD; k++)
                    a2 += __bfloat162float(__float2bfloat16(x[(size_t)row * DD + k])) * __bfloat162float(w[k]);
                h1v[n] = fmaxf(a2, 0.f);
            }
            for (int n = 0; n < 128; n++) {
                float a2 = b2[n];
                const __nv_bfloat16* w = w2t + (size_t)n * HH1;
                for (int k = 0; k < HH1; k++)
                    a2 += __bfloat162float(__float2bfloat16(h1v[k])) * __bfloat162float(w[k]);
                h2v[n] = fmaxf(a2, 0.f);
            }
            for (int n = 0; n < 64; n++) {
                float a2 = b3[n];
                const __nv_bfloat16* w = w3t + (size_t)n * HH2;
                for (int k = 0; k < HH2; k++)
                    a2 += __bfloat162float(__float2bfloat16(h2v[k])) * __bfloat162float(w[k]);
                d[n] = a2;
            }
            float mx = -1e30f;
            for (int j = 0; j < 64; j++) {
                d[j] = (d[j] - vlnf(-vlnf(u[(size_t)row * 64 + j]))) * tinv;
                mx = fmaxf(mx, d[j]);
            }
            float sum = 0.f;
            for (int j = 0; j < 64; j++) { d[j] = vexpf(d[j] - mx); sum += d[j]; }
            float rs = 1.0f / sum, sel = 0.f;
            for (int j = 0; j < 64; j++) {
                float a2 = 0.f;
                const __nv_bfloat16* w = tt + (size_t)j * DD;
                for (int k = 0; k < DD; k++)
                    a2 += __bfloat162float(__float2bfloat16(x[(size_t)row * DD + k])) * __bfloat162float(w[k]);
                sel = fmaf(a2, d[j] * rs, sel);
            }
            float diff = sel - label[row];
            accp += diff * diff * (1.0f / (float)BB);
        }
    }
    for (int o = 16; o; o >>= 1) accp += __shfl_xor_sync(0xffffffffu, accp, o);
    if ((tid & 31) == 0) red[tid >> 5] = accp;
    __syncthreads();
    if (tid == 0) {
        float sfin = 0.f;
        for (int w = 0; w < 16; w++) sfin += red[w];
        atomicAdd(out, sfin);
    }
#endif
}

// ---------------------------------------------------------------------------
extern "C" void kernel_launch(void* const* d_in, const int* in_sizes, int n_in,
                              void* d_out, int out_size)
{
    const float* x      = (const float*)d_in[0];
    const float* label  = (const float*)d_in[1];
    const float* u      = (const float*)d_in[2];
    const float* W1     = (const float*)d_in[3];
    const float* b1     = (const float*)d_in[4];
    const float* W2     = (const float*)d_in[5];
    const float* b2     = (const float*)d_in[6];
    const float* W3     = (const float*)d_in[7];
    const float* b3     = (const float*)d_in[8];
    const float* thetas = (const float*)d_in[9];
    const int*   epoch  = (const int*)d_in[10];
    float* out = (float*)d_out;

    __nv_bfloat16 *w1t, *w2t, *w3t, *tt;
    cudaGetSymbolAddress((void**)&w1t, g_w1t);
    cudaGetSymbolAddress((void**)&w2t, g_w2t);
    cudaGetSymbolAddress((void**)&w3t, g_w3t);
    cudaGetSymbolAddress((void**)&tt,  g_tt);

    cudaFuncSetAttribute(fused_llp, cudaFuncAttributeMaxDynamicSharedMemorySize, SMEM_SIZE);

    cudaMemsetAsync(out, 0, (size_t)out_size * sizeof(float), 0);

    transpose_all<<<800, 256>>>(W1, W2, W3, thetas, w1t, w2t, w3t, tt);

    fused_llp<<<GRID, 512, SMEM_SIZE>>>(x, u, label, w1t, w2t, w3t, tt,
                                        b1, b2, b3, epoch, out);
}

// round 9
// speedup vs baseline: 1.5434x; 1.5434x over previous
#include <cuda_runtime.h>
#include <cuda_bf16.h>
#include <cstdint>

#ifndef __CUDA_ARCH_HAS_FEATURE__
#define __CUDA_ARCH_HAS_FEATURE__(x) 0
#endif
#if defined(__CUDA_ARCH_FEAT_SM103_ALL) || __CUDA_ARCH_HAS_FEATURE__(SM103_ALL) || \
    defined(__CUDA_ARCH_FEAT_SM100_ALL) || __CUDA_ARCH_HAS_FEATURE__(SM100_ALL)
#define HAS_TCGEN05 1
#else
#define HAS_TCGEN05 0
#endif

static constexpr int BB  = 65536;
static constexpr int DD  = 512;
static constexpr int HH1 = 256;
static constexpr int HH2 = 128;
static constexpr int NTILES = BB / 128;   // 512
static constexpr int GRID = 148;

__device__ __nv_bfloat16 g_w1t[HH1 * DD];
__device__ __nv_bfloat16 g_w2t[HH2 * HH1];
__device__ __nv_bfloat16 g_w3t[64 * HH2];
__device__ __nv_bfloat16 g_tt [64 * DD];

// ---------------- PTX helpers ----------------------------------------------
__device__ __forceinline__ uint32_t smem_u32(const void* p) {
    uint32_t a;
    asm("{ .reg .u64 t; cvta.to.shared.u64 t, %1; cvt.u32.u64 %0, t; }" : "=r"(a) : "l"(p));
    return a;
}
#define MBAR_INIT(addr, cnt) \
    asm volatile("mbarrier.init.shared.b64 [%0], %1;" :: "r"(addr), "r"(cnt) : "memory")
#define MBAR_ARRIVE(addr) \
    asm volatile("mbarrier.arrive.shared.b64 _, [%0];" :: "r"(addr) : "memory")
#define MBAR_WAIT(addr, parity) do {                                              \
    asm volatile("{\n\t.reg .pred P;\n\tWL%=:\n\t"                                \
        "mbarrier.try_wait.parity.acquire.cta.shared::cta.b64 P, [%0], %1, 0x989680;\n\t" \
        "@P bra.uni WD%=;\n\tbra.uni WL%=;\n\tWD%=:\n\t}"                          \
        :: "r"(addr), "r"(parity) : "memory");                                    \
} while (0)
#define TC_ALLOC(smem_dst, n) \
    asm volatile("tcgen05.alloc.cta_group::1.sync.aligned.shared::cta.b32 [%0], %1;" :: "r"(smem_dst), "r"(n) : "memory")
#define TC_DEALLOC(tmem, n) \
    asm volatile("tcgen05.dealloc.cta_group::1.sync.aligned.b32 %0, %1;" :: "r"(tmem), "r"(n))
#define TC_RELINQ() \
    asm volatile("tcgen05.relinquish_alloc_permit.cta_group::1.sync.aligned;")
#define TC_COMMIT(mbar) \
    asm volatile("tcgen05.commit.cta_group::1.mbarrier::arrive::one.shared::cluster.b64 [%0];" :: "r"(mbar) : "memory")
#define TC_FENCE_AFTER()   asm volatile("tcgen05.fence::after_thread_sync;" ::: "memory")
#define TC_FENCE_BEFORE()  asm volatile("tcgen05.fence::before_thread_sync;" ::: "memory")
#define TC_WAIT_LD()       asm volatile("tcgen05.wait::ld.sync.aligned;" ::: "memory")
#define TC_WAIT_ST()       asm volatile("tcgen05.wait::st.sync.aligned;" ::: "memory")
#define FENCE_ASYNC()      asm volatile("fence.proxy.async.shared::cta;" ::: "memory")
#define BARC()             asm volatile("bar.sync 1, 256;" ::: "memory")

#define CP_ASYNC16(dst, src) \
    asm volatile("cp.async.cg.shared.global [%0], [%1], 16;" :: "r"(dst), "l"(src) : "memory")
#define CP_COMMIT() asm volatile("cp.async.commit_group;" ::: "memory")
#define CP_WAIT(n)  asm volatile("cp.async.wait_group %0;" :: "n"(n) : "memory")

#define TC_LD_X32(r, tmem_addr) \
    asm volatile( \
        "tcgen05.ld.sync.aligned.32x32b.x32.b32 " \
        "{%0, %1, %2, %3, %4, %5, %6, %7, " \
        " %8, %9, %10, %11, %12, %13, %14, %15, " \
        " %16, %17, %18, %19, %20, %21, %22, %23, " \
        " %24, %25, %26, %27, %28, %29, %30, %31}, [%32];" \
        : "=r"((r)[0]),  "=r"((r)[1]),  "=r"((r)[2]),  "=r"((r)[3]), \
          "=r"((r)[4]),  "=r"((r)[5]),  "=r"((r)[6]),  "=r"((r)[7]), \
          "=r"((r)[8]),  "=r"((r)[9]),  "=r"((r)[10]), "=r"((r)[11]), \
          "=r"((r)[12]), "=r"((r)[13]), "=r"((r)[14]), "=r"((r)[15]), \
          "=r"((r)[16]), "=r"((r)[17]), "=r"((r)[18]), "=r"((r)[19]), \
          "=r"((r)[20]), "=r"((r)[21]), "=r"((r)[22]), "=r"((r)[23]), \
          "=r"((r)[24]), "=r"((r)[25]), "=r"((r)[26]), "=r"((r)[27]), \
          "=r"((r)[28]), "=r"((r)[29]), "=r"((r)[30]), "=r"((r)[31]) \
        : "r"(tmem_addr))

#define TC_ST_X16(tmem_addr, r) \
    asm volatile( \
        "tcgen05.st.sync.aligned.32x32b.x16.b32 [%0], " \
        "{%1, %2, %3, %4, %5, %6, %7, %8, " \
        " %9, %10, %11, %12, %13, %14, %15, %16};" \
        :: "r"(tmem_addr), \
           "r"((r)[0]),  "r"((r)[1]),  "r"((r)[2]),  "r"((r)[3]), \
           "r"((r)[4]),  "r"((r)[5]),  "r"((r)[6]),  "r"((r)[7]), \
           "r"((r)[8]),  "r"((r)[9]),  "r"((r)[10]), "r"((r)[11]), \
           "r"((r)[12]), "r"((r)[13]), "r"((r)[14]), "r"((r)[15]) \
        : "memory")

#if HAS_TCGEN05
__device__ __forceinline__ void mma_f16_ss(uint32_t d, uint64_t ad, uint64_t bd,
                                           uint32_t idesc, uint32_t en) {
    asm volatile(
        "{\n\t.reg .pred p;\n\tsetp.ne.u32 p, %4, 0;\n\t"
        "tcgen05.mma.cta_group::1.kind::f16 [%0], %1, %2, %3, {%5, %5, %5, %5}, p;\n\t}"
        :: "r"(d), "l"(ad), "l"(bd), "r"(idesc), "r"(en), "r"(0u) : "memory");
}
__device__ __forceinline__ void mma_f16_ts(uint32_t d, uint32_t a_tmem, uint64_t bd,
                                           uint32_t idesc, uint32_t en) {
    asm volatile(
        "{\n\t.reg .pred p;\n\tsetp.ne.u32 p, %4, 0;\n\t"
        "tcgen05.mma.cta_group::1.kind::f16 [%0], [%1], %2, %3, {%5, %5, %5, %5}, p;\n\t}"
        :: "r"(d), "r"(a_tmem), "l"(bd), "r"(idesc), "r"(en), "r"(0u) : "memory");
}
#endif

__device__ __forceinline__ uint64_t make_desc(uint32_t addr) {      // SW128, 128B rows
    const uint64_t base = (2ull << 61) | (1ull << 46) | (64ull << 32) | (1ull << 16);
    return base | ((uint64_t)(addr >> 4) & 0x3FFF);
}
__device__ __forceinline__ uint64_t make_desc64(uint32_t addr) {    // SW64, 64B rows
    const uint64_t base = (4ull << 61) | (1ull << 46) | (32ull << 32) | (1ull << 16);
    return base | ((uint64_t)(addr >> 4) & 0x3FFF);
}
__device__ __forceinline__ uint32_t sw128(uint32_t o) { return o ^ ((o >> 3) & 0x70); }
__device__ __forceinline__ uint32_t sw64(uint32_t o)  { return o ^ ((o >> 3) & 0x30); }
__device__ __forceinline__ uint32_t pack_bf2(float a, float b) {
    uint32_t r;
    asm("cvt.rn.satfinite.bf16x2.f32 %0, %1, %2;" : "=r"(r) : "f"(b), "f"(a));
    return r;
}
static __host__ __device__ constexpr uint32_t idesc_n(int N) {
    return (1u << 4) | (1u << 7) | (1u << 10) | ((uint32_t)(N / 8) << 17) | (8u << 24);
}

// ---- FFMA-only ln/exp ------------------------------------------------------
__device__ __forceinline__ float vlnf(float x) {
    int i = __float_as_int(x);
    float e = (float)((i >> 23) - 126);
    float m = __int_as_float((i & 0x007FFFFF) | 0x3F000000);
    if (m < 0.70710678f) { m += m; e -= 1.0f; }
    float z = m - 1.0f, w = z * z;
    float p =              7.0376836292e-2f;
    p = fmaf(p, z, -1.1514610310e-1f);
    p = fmaf(p, z,  1.1676998740e-1f);
    p = fmaf(p, z, -1.2420140846e-1f);
    p = fmaf(p, z,  1.4249322787e-1f);
    p = fmaf(p, z, -1.6668057665e-1f);
    p = fmaf(p, z,  2.0000714765e-1f);
    p = fmaf(p, z, -2.4999993993e-1f);
    p = fmaf(p, z,  3.3333331174e-1f);
    float r = fmaf(z * w, p, fmaf(-0.5f, w, z));
    return fmaf(e, 0.693147180559945f, r);
}
__device__ __forceinline__ float vexpf(float x) {
    float t = fmaxf(x * 1.4426950408889634f, -125.0f);
    int ni = __float2int_rn(t);
    float f = t - (float)ni;
    float p =              1.53533619e-4f;
    p = fmaf(p, f, 1.33988744e-3f);
    p = fmaf(p, f, 9.61843736e-3f);
    p = fmaf(p, f, 5.55033250e-2f);
    p = fmaf(p, f, 2.40226479e-1f);
    p = fmaf(p, f, 6.93147203e-1f);
    p = fmaf(p, f, 1.0f);
    return p * __int_as_float((ni + 127) << 23);
}
__device__ __forceinline__ float temp_of(float ep) {
    return fmaxf(0.1f, 10.0f * vexpf(-4.60517018598809f * ep * 0.001f));
}

// ---------------- weight transpose + bf16 convert ---------------------------
__global__ void transpose_all(const float* __restrict__ W1, const float* __restrict__ W2,
                              const float* __restrict__ W3, const float* __restrict__ Th,
                              __nv_bfloat16* __restrict__ w1t, __nv_bfloat16* __restrict__ w2t,
                              __nv_bfloat16* __restrict__ w3t, __nv_bfloat16* __restrict__ tt)
{
    int idx = blockIdx.x * 256 + threadIdx.x;
    if (idx < 131072) {
        int r = idx >> 8, c = idx & 255;
        w1t[c * DD + r] = __float2bfloat16(W1[idx]);
    } else if (idx < 163840) {
        int q = idx - 131072; int r = q >> 7, c = q & 127;
        w2t[c * HH1 + r] = __float2bfloat16(W2[q]);
    } else if (idx < 172032) {
        int q = idx - 163840; int r = q >> 6, c = q & 63;
        w3t[c * HH2 + r] = __float2bfloat16(W3[q]);
    } else if (idx < 204800) {
        int q = idx - 172032; int r = q >> 6, c = q & 63;
        tt[c * DD + r] = __float2bfloat16(Th[q]);
    }
}

// ---------------- SMEM map --------------------------------------------------
// 0 tmemptr | CHF 8/16/24 (cnt 224) CFR 32/40/48 | P1D 56 P2D 64 P3D 72 P4D 80 P5D 88
// B1 128 B2 1280 B3 1824 | PMX 2048 PSM 3072 PDT 4096 RED 5120
// STG 3x16KB @8192 | ABF 3x8KB @57344 | BRG 3x20KB @81920 | W2T 64KB @143360 | W3T 16KB @208896
static constexpr int SMEM_SIZE = 225280;

__global__ __launch_bounds__(512, 1) void fused_llp(
    const float* __restrict__ x, const float* __restrict__ u,
    const float* __restrict__ label,
    const __nv_bfloat16* __restrict__ w1t, const __nv_bfloat16* __restrict__ w2t,
    const __nv_bfloat16* __restrict__ w3t, const __nv_bfloat16* __restrict__ tt,
    const float* __restrict__ b1, const float* __restrict__ b2,
    const float* __restrict__ b3, const int* __restrict__ epochp,
    float* __restrict__ out)
{
#if HAS_TCGEN05
    constexpr uint32_t CHF0 = 8, CFR0 = 32;
    constexpr uint32_t P1D = 56, P2D = 64, P3D = 72, P4D = 80, P5D = 88;
    constexpr uint32_t B1O = 128, B2O = 1280, B3O = 1824;
    constexpr uint32_t PMX = 2048, PSM = 3072, PDT = 4096, RED = 5120;
    constexpr uint32_t STG0 = 8192, ABF0 = 57344, BRG0 = 81920;
    constexpr uint32_t W2TO = 143360, W3TO = 208896;
    constexpr uint32_t IDB1 = idesc_n(256), IDT = idesc_n(64);
    constexpr uint32_t IDB2 = idesc_n(128), IDB3 = idesc_n(64);
    // TMEM: h1 f32 @0-255 (bf16 reuse @0-127) | xt @256-319 | h2 f32 @320-447
    //       (bf16 reuse @320-383) | logits @448-511

    extern __shared__ char smem[];
    const uint32_t sb = smem_u32(smem);
    const int tid = threadIdx.x;
    const int wid = tid >> 5;
    const int lane = tid & 31;
    const int bid = blockIdx.x;
    const int ntiles = (NTILES - 1 - bid) / GRID + 1;

    // ---------------- prologue (all threads) ----------------
    if (wid == 0) TC_ALLOC(sb + 0, 512);
    if (tid == 0) {
        MBAR_INIT(sb + CHF0, 224); MBAR_INIT(sb + CHF0 + 8, 224); MBAR_INIT(sb + CHF0 + 16, 224);
        MBAR_INIT(sb + CFR0, 1);   MBAR_INIT(sb + CFR0 + 8, 1);   MBAR_INIT(sb + CFR0 + 16, 1);
        MBAR_INIT(sb + P1D, 1); MBAR_INIT(sb + P2D, 1); MBAR_INIT(sb + P3D, 1);
        MBAR_INIT(sb + P4D, 1); MBAR_INIT(sb + P5D, 1);
    }
    if (tid < 256) ((float*)(smem + B1O))[tid] = b1[tid];
    else if (tid < 384) ((float*)(smem + B2O))[tid - 256] = b2[tid - 256];
    else if (tid < 448) ((float*)(smem + B3O))[tid - 384] = b3[tid - 384];
    // W2T: 128 rows x 256k -> 4 K-blocks of 128x64 (16KB each, SW128)
#pragma unroll
    for (int i = 0; i < 8; i++) {
        int q = tid + i * 512;
        int n = q >> 5, j = q & 31, kb = j >> 3, ku = j & 7;
        uint4 v = *(const uint4*)(w2t + (size_t)n * HH1 + j * 8);
        *(uint4*)(smem + W2TO + kb * 16384 + sw128(n * 128 + ku * 16)) = v;
    }
    // W3T: 64 rows x 128k -> 2 K-blocks of 64x64 (8KB each, SW128)
#pragma unroll
    for (int i = 0; i < 2; i++) {
        int q = tid + i * 512;
        int n = q >> 4, j = q & 15, kb = j >> 3, ku = j & 7;
        uint4 v = *(const uint4*)(w3t + (size_t)n * HH2 + j * 8);
        *(uint4*)(smem + W3TO + kb * 8192 + sw128(n * 128 + ku * 16)) = v;
    }
    FENCE_ASYNC();
    __syncthreads();
    uint32_t tmem;
    asm volatile("ld.shared.b32 %0, [%1];" : "=r"(tmem) : "r"(sb + 0));

    const float tinv = 1.0f / temp_of((float)(*epochp));
    const int total = ntiles * 16;   // K-chunks of 32, 16 per tile

    // =======================================================================
    if (wid >= 9) {
        // ---------------- PRODUCERS (warps 9-15, 224 threads) --------------
        const int pt = tid - 288;
        auto issue_group = [&](int g) {
            const int ttg = g >> 4, cg = g & 15, slot = g % 3;
            const int m0g = (bid + ttg * GRID) * 128;
            // B chunk: 320 rows x 32k bf16, 64B rows -> SW64  (1280 x 16B)
            for (int i = pt; i < 1280; i += 224) {
                int row = i >> 2, seg = i & 3;
                const __nv_bfloat16* src = (row >= 256)
                    ? (tt  + (size_t)(row - 256) * DD + cg * 32 + seg * 8)
                    : (w1t + (size_t)row * DD + cg * 32 + seg * 8);
                CP_ASYNC16(sb + BRG0 + slot * 20480 + sw64(row * 64 + seg * 16), src);
            }
            // x chunk: 128 rows x 32 fp32, linear 128B rows  (1024 x 16B)
            for (int i = pt; i < 1024; i += 224) {
                int row = i >> 3, seg = i & 7;
                CP_ASYNC16(sb + STG0 + slot * 16384 + row * 128 + seg * 16,
                           x + (size_t)(m0g + row) * DD + cg * 32 + seg * 4);
            }
            CP_COMMIT();
        };
        issue_group(0); issue_group(1);
        int cfrc[3] = {0, 0, 0};
        for (int gc = 0; gc < total; gc++) {
            const int g = gc + 2;
            if (g < total) {
                const int s = g % 3;
                if (g >= 3) { MBAR_WAIT(sb + CFR0 + 8 * s, cfrc[s] & 1); cfrc[s]++; }
                issue_group(g);
                CP_WAIT(2);
            } else {
                CP_WAIT(0);
            }
            // convert STG[slot] fp32 -> ABF[slot] bf16 (SW64)
            const int slot = gc % 3;
            for (int i = pt; i < 512; i += 224) {
                int row = i >> 2, sg = i & 3;
                const float4* sp = (const float4*)(smem + STG0 + slot * 16384 + row * 128 + sg * 32);
                float4 f0 = sp[0], f1 = sp[1];
                uint4 v = make_uint4(pack_bf2(f0.x, f0.y), pack_bf2(f0.z, f0.w),
                                     pack_bf2(f1.x, f1.y), pack_bf2(f1.z, f1.w));
                *(uint4*)(smem + ABF0 + slot * 8192 + sw64(row * 64 + sg * 16)) = v;
            }
            FENCE_ASYNC();
            MBAR_ARRIVE(sb + CHF0 + 8 * slot);
        }
    } else if (wid == 8) {
        // ---------------- MMA warp (lane 0 only) ---------------------------
        if (lane == 0) {
            int gc = 0;
            int chfc[3] = {0, 0, 0};
            int p2c = 0, p4c = 0;
            auto issue_chunk = [&]() {
                const int slot = gc % 3;
                const int c = gc & 15;
                MBAR_WAIT(sb + CHF0 + 8 * slot, chfc[slot] & 1); chfc[slot]++;
                uint64_t ad = make_desc64(sb + ABF0 + slot * 8192);
                uint64_t bd = make_desc64(sb + BRG0 + slot * 20480);
                uint64_t td = make_desc64(sb + BRG0 + slot * 20480 + 16384);
#pragma unroll
                for (int s = 0; s < 2; s++) {
                    uint32_t en = (c > 0 || s > 0) ? 1u : 0u;
                    mma_f16_ss(tmem, ad + 2 * s, bd + 2 * s, IDB1, en);
                    mma_f16_ss(tmem + 256, ad + 2 * s, td + 2 * s, IDT, en);
                }
                TC_COMMIT(sb + CFR0 + 8 * slot);
                if (c == 15) TC_COMMIT(sb + P1D);
                gc++;
            };
            for (int c = 0; c < 16; c++) issue_chunk();    // tile 0
            for (int tti = 0; tti < ntiles; tti++) {
                // P3: h1bf16(TMEM 0-127) @ W2T -> h2 (K=256, 16 steps)
                MBAR_WAIT(sb + P2D, p2c & 1); p2c++;
                TC_FENCE_AFTER();
#pragma unroll
                for (int s = 0; s < 16; s++) {
                    uint64_t bd = make_desc(sb + W2TO + (uint32_t)(s >> 2) * 16384u) + (s & 3) * 2;
                    mma_f16_ts(tmem + 320, tmem + s * 8, bd, IDB2, s > 0 ? 1u : 0u);
                }
                TC_COMMIT(sb + P3D);
                if (tti + 1 < ntiles) for (int c = 0; c < 4; c++) issue_chunk();
                // P5: h2bf16(TMEM 320-383) @ W3T -> logits (K=128, 8 steps)
                MBAR_WAIT(sb + P4D, p4c & 1); p4c++;
                TC_FENCE_AFTER();
#pragma unroll
                for (int s = 0; s < 8; s++) {
                    uint64_t bd = make_desc(sb + W3TO + (uint32_t)(s >> 2) * 8192u) + (s & 3) * 2;
                    mma_f16_ts(tmem + 448, tmem + 320 + s * 8, bd, IDB3, s > 0 ? 1u : 0u);
                }
                TC_COMMIT(sb + P5D);
                if (tti + 1 < ntiles) for (int c = 0; c < 12; c++) issue_chunk();
            }
        }
    } else {
        // ---------------- CONSUMERS (warps 0-7, 256 threads) ---------------
        const int w = wid;
        const int sub = w & 3;
        const int half = w >> 2;
        const int tr = sub * 32 + lane;
        int cp1 = 0, cp3 = 0, cp5 = 0;
        float acc = 0.f;
        const float* sb1 = (const float*)(smem + B1O);
        const float* sb2 = (const float*)(smem + B2O);
        const float* sb3 = (const float*)(smem + B3O);
        float* pmax = (float*)(smem + PMX);
        float* psum = (float*)(smem + PSM);
        float* pdot = (float*)(smem + PDT);

        for (int t = bid; t < NTILES; t += GRID) {
            const int m0 = t * 128;
            // ---- P2: h1 epilogue -> TMEM bf16 ; xt -> regs ----
            MBAR_WAIT(sb + P1D, cp1 & 1); cp1++;
            TC_FENCE_AFTER();
            uint32_t pk[64];
            {
                uint32_t r[32];
#pragma unroll
                for (int ch = 0; ch < 4; ch++) {
                    const int cb = half * 128 + ch * 32;
                    TC_LD_X32(r, tmem + cb);
                    TC_WAIT_LD();
#pragma unroll
                    for (int i = 0; i < 16; i++) {
                        float a = __uint_as_float(r[2 * i + 0]) + sb1[cb + 2 * i + 0];
                        float b = __uint_as_float(r[2 * i + 1]) + sb1[cb + 2 * i + 1];
                        pk[ch * 16 + i] = pack_bf2(fmaxf(a, 0.f), fmaxf(b, 0.f));
                    }
                }
            }
            BARC();
#pragma unroll
            for (int ch = 0; ch < 4; ch++)
                TC_ST_X16(tmem + half * 64 + ch * 16, pk + ch * 16);
            float xtv[32];
            {
                uint32_t r[32];
                TC_LD_X32(r, tmem + 256 + half * 32);
                TC_WAIT_LD();
#pragma unroll
                for (int j = 0; j < 32; j++) xtv[j] = __uint_as_float(r[j]);
            }
            TC_WAIT_ST();
            TC_FENCE_BEFORE();
            BARC();
            if (tid == 0) MBAR_ARRIVE(sb + P2D);

            // prefetch u + label for this tile
            float4 uu[8];
            {
                const float4* up = (const float4*)(u + (size_t)(m0 + tr) * 64 + half * 32);
#pragma unroll
                for (int q = 0; q < 8; q++) uu[q] = up[q];
            }
            float lb = 0.f;
            if (half == 0) lb = __ldg(&label[m0 + tr]);

            // ---- P4: h2 epilogue -> TMEM bf16 ----
            MBAR_WAIT(sb + P3D, cp3 & 1); cp3++;
            TC_FENCE_AFTER();
            uint32_t pk2[32];
            {
                uint32_t r[32];
#pragma unroll
                for (int ch = 0; ch < 2; ch++) {
                    const int cb = 320 + half * 64 + ch * 32;
                    TC_LD_X32(r, tmem + cb);
                    TC_WAIT_LD();
#pragma unroll
                    for (int i = 0; i < 16; i++) {
                        float a = __uint_as_float(r[2 * i + 0]) + sb2[cb - 320 + 2 * i + 0];
                        float b = __uint_as_float(r[2 * i + 1]) + sb2[cb - 320 + 2 * i + 1];
                        pk2[ch * 16 + i] = pack_bf2(fmaxf(a, 0.f), fmaxf(b, 0.f));
                    }
                }
            }
            BARC();
#pragma unroll
            for (int ch = 0; ch < 2; ch++)
                TC_ST_X16(tmem + 320 + half * 32 + ch * 16, pk2 + ch * 16);
            TC_WAIT_ST();
            TC_FENCE_BEFORE();
            BARC();
            if (tid == 0) MBAR_ARRIVE(sb + P4D);

            // ---- P6: gumbel softmax + row-dot + MSE ----
            MBAR_WAIT(sb + P5D, cp5 & 1); cp5++;
            TC_FENCE_AFTER();
            float s[32];
            {
                uint32_t r[32];
                TC_LD_X32(r, tmem + 448 + half * 32);
                TC_WAIT_LD();
#pragma unroll
                for (int j = 0; j < 32; j++) s[j] = __uint_as_float(r[j]) + sb3[half * 32 + j];
            }
            float mx = -1e30f;
#pragma unroll
            for (int q = 0; q < 8; q++) {
                float4 ug = uu[q];
                float g0 = -vlnf(-vlnf(ug.x));
                float g1 = -vlnf(-vlnf(ug.y));
                float g2 = -vlnf(-vlnf(ug.z));
                float g3 = -vlnf(-vlnf(ug.w));
                s[4 * q + 0] = (s[4 * q + 0] + g0) * tinv;
                s[4 * q + 1] = (s[4 * q + 1] + g1) * tinv;
                s[4 * q + 2] = (s[4 * q + 2] + g2) * tinv;
                s[4 * q + 3] = (s[4 * q + 3] + g3) * tinv;
                mx = fmaxf(mx, fmaxf(fmaxf(s[4 * q], s[4 * q + 1]), fmaxf(s[4 * q + 2], s[4 * q + 3])));
            }
            pmax[tr * 2 + half] = mx;
            BARC();
            mx = fmaxf(pmax[tr * 2], pmax[tr * 2 + 1]);
            float sum = 0.f, dot = 0.f;
#pragma unroll
            for (int j = 0; j < 32; j++) {
                float e = vexpf(s[j] - mx);
                sum += e;
                dot = fmaf(xtv[j], e, dot);
            }
            psum[tr * 2 + half] = sum;
            pdot[tr * 2 + half] = dot;
            BARC();
            if (half == 0) {
                float tsum = psum[tr * 2] + psum[tr * 2 + 1];
                float tdot = pdot[tr * 2] + pdot[tr * 2 + 1];
                float diff = tdot / tsum - lb;
                acc = fmaf(diff, diff, acc);
            }
        }
        if (half == 0) {
            acc *= (1.0f / (float)BB);
#pragma unroll
            for (int o = 16; o; o >>= 1) acc += __shfl_xor_sync(0xffffffffu, acc, o);
            if (lane == 0) ((float*)(smem + RED))[w] = acc;
        }
    }

    __syncthreads();
    if (tid == 0) {
        float* red = (float*)(smem + RED);
        atomicAdd(out, red[0] + red[1] + red[2] + red[3]);
    }
    if (wid == 0) { TC_RELINQ(); TC_DEALLOC(tmem, 512); }

#else  // ------------------- SIMT fallback (generic PTX pass only) ----------
    extern __shared__ char smem[];
    float* red = (float*)smem;
    const int tid = threadIdx.x;
    const float tinv = 1.0f / temp_of((float)(*epochp));
    float accp = 0.f;
    for (int t = blockIdx.x; t < NTILES; t += GRID) {
        const int m0 = t * 128;
        if (tid < 128) {
            const int row = m0 + tid;
            float h1v[256], h2v[128], d[64];
            for (int n = 0; n < 256; n++) {
                float a2 = b1[n];
                const __nv_bfloat16* w = w1t + (size_t)n * DD;
                for (int k = 0; k < DD; k++)
                    a2 += __bfloat162float(__float2bfloat16(x[(size_t)row * DD + k])) * __bfloat162float(w[k]);
                h1v[n] = fmaxf(a2, 0.f);
            }
            for (int n = 0; n < 128; n++) {
                float a2 = b2[n];
                const __nv_bfloat16* w = w2t + (size_t)n * HH1;
                for (int k = 0; k < HH1; k++)
                    a2 += __bfloat162float(__float2bfloat16(h1v[k])) * __bfloat162float(w[k]);
                h2v[n] = fmaxf(a2, 0.f);
            }
            for (int n = 0; n < 64; n++) {
                float a2 = b3[n];
                const __nv_bfloat16* w = w3t + (size_t)n * HH2;
                for (int k = 0; k < HH2; k++)
                    a2 += __bfloat162float(__float2bfloat16(h2v[k])) * __bfloat162float(w[k]);
                d[n] = a2;
            }
            float mx = -1e30f;
            for (int j = 0; j < 64; j++) {
                d[j] = (d[j] - vlnf(-vlnf(u[(size_t)row * 64 + j]))) * tinv;
                mx = fmaxf(mx, d[j]);
            }
            float sum = 0.f;
            for (int j = 0; j < 64; j++) { d[j] = vexpf(d[j] - mx); sum += d[j]; }
            float rs = 1.0f / sum, sel = 0.f;
            for (int j = 0; j < 64; j++) {
                float a2 = 0.f;
                const __nv_bfloat16* w = tt + (size_t)j * DD;
                for (int k = 0; k < DD; k++)
                    a2 += __bfloat162float(__float2bfloat16(x[(size_t)row * DD + k])) * __bfloat162float(w[k]);
                sel = fmaf(a2, d[j] * rs, sel);
            }
            float diff = sel - label[row];
            accp += diff * diff * (1.0f / (float)BB);
        }
    }
    for (int o = 16; o; o >>= 1) accp += __shfl_xor_sync(0xffffffffu, accp, o);
    if ((tid & 31) == 0) red[tid >> 5] = accp;
    __syncthreads();
    if (tid == 0) {
        float sfin = 0.f;
        for (int w = 0; w < 16; w++) sfin += red[w];
        atomicAdd(out, sfin);
    }
#endif
}

// ---------------------------------------------------------------------------
extern "C" void kernel_launch(void* const* d_in, const int* in_sizes, int n_in,
                              void* d_out, int out_size)
{
    const float* x      = (const float*)d_in[0];
    const float* label  = (const float*)d_in[1];
    const float* u      = (const float*)d_in[2];
    const float* W1     = (const float*)d_in[3];
    const float* b1     = (const float*)d_in[4];
    const float* W2     = (const float*)d_in[5];
    const float* b2     = (const float*)d_in[6];
    const float* W3     = (const float*)d_in[7];
    const float* b3     = (const float*)d_in[8];
    const float* thetas = (const float*)d_in[9];
    const int*   epoch  = (const int*)d_in[10];
    float* out = (float*)d_out;

    __nv_bfloat16 *w1t, *w2t, *w3t, *tt;
    cudaGetSymbolAddress((void**)&w1t, g_w1t);
    cudaGetSymbolAddress((void**)&w2t, g_w2t);
    cudaGetSymbolAddress((void**)&w3t, g_w3t);
    cudaGetSymbolAddress((void**)&tt,  g_tt);

    cudaFuncSetAttribute(fused_llp, cudaFuncAttributeMaxDynamicSharedMemorySize, SMEM_SIZE);

    cudaMemsetAsync(out, 0, (size_t)out_size * sizeof(float), 0);

    transpose_all<<<800, 256>>>(W1, W2, W3, thetas, w1t, w2t, w3t, tt);

    fused_llp<<<GRID, 512, SMEM_SIZE>>>(x, u, label, w1t, w2t, w3t, tt,
                                        b1, b2, b3, epoch, out);
}